// round 1
// baseline (speedup 1.0000x reference)
#include <cuda_runtime.h>
#include <cuda_bf16.h>
#include <cstdint>

// Problem constants
#define NQ      8192        // B*S queries
#define CDIM    512         // feature dim (K of the GEMM)
#define MROWS   32768       // memory table rows
#define TOPK    5
#define NCH     8           // M chunks (candidate stage)
#define MCHUNK  (MROWS/NCH) // 4096
#define NCAND   (NCH*TOPK)  // 40

// GEMM tiling
#define QT        128       // queries per block
#define NT        64        // memory rows per inner tile
#define KC        64        // k-chunk for M tile streaming
#define NKC       (CDIM/KC) // 8
#define MT_PER    (MCHUNK/NT) // 64
#define SQ_STRIDE 520       // bf16 elems per sQ row (512 + 8 pad)
#define SM_STRIDE 72        // bf16 elems per sM row (64 + 8 pad)
#define SS_STRIDE 65        // floats per sSim row (64 + 1 pad)

#define SMEM_BYTES (QT*SQ_STRIDE*2 + 2*NT*SM_STRIDE*2 + QT*SS_STRIDE*4) // 184832

// Scratch (device globals: allocation-free)
__device__ __nv_bfloat16 g_qn[(size_t)NQ*CDIM];
__device__ __nv_bfloat16 g_mn[(size_t)MROWS*CDIM];
__device__ float g_minv[MROWS];
__device__ float g_cscore[(size_t)NQ*NCAND];
__device__ int   g_cidx[(size_t)NQ*NCAND];

__device__ __forceinline__ uint32_t smem_u32(const void* p){
    return (uint32_t)__cvta_generic_to_shared(p);
}
__device__ __forceinline__ float warp_sum(float v){
    #pragma unroll
    for (int o=16;o;o>>=1) v += __shfl_xor_sync(0xffffffffu, v, o);
    return v;
}

// ---------------------------------------------------------------------------
// Kernel 1/2: L2-normalize rows (fp32 in -> bf16 out). MODE 0: queries, 1: memory.
// One warp per row; 256 threads = 8 rows/block.
// ---------------------------------------------------------------------------
template<int MODE>
__global__ void normalize_kernel(const float* __restrict__ in){
    const int rows = MODE ? MROWS : NQ;
    __nv_bfloat16* outb = MODE ? g_mn : g_qn;
    int row  = blockIdx.x*8 + (threadIdx.x >> 5);
    int lane = threadIdx.x & 31;
    if (row >= rows) return;
    const float4* src = (const float4*)(in + (size_t)row*CDIM);
    float4 v[4];
    float ss = 0.f;
    #pragma unroll
    for (int w=0; w<4; w++){
        v[w] = src[lane + w*32];
        ss += v[w].x*v[w].x + v[w].y*v[w].y + v[w].z*v[w].z + v[w].w*v[w].w;
    }
    ss = warp_sum(ss);
    float inv = 1.0f / fmaxf(sqrtf(ss), 1e-12f);
    __nv_bfloat16* dst = outb + (size_t)row*CDIM;
    #pragma unroll
    for (int w=0; w<4; w++){
        __nv_bfloat162 p0 = __floats2bfloat162_rn(v[w].x*inv, v[w].y*inv);
        __nv_bfloat162 p1 = __floats2bfloat162_rn(v[w].z*inv, v[w].w*inv);
        uint2 st;
        st.x = *(uint32_t*)&p0;
        st.y = *(uint32_t*)&p1;
        *(uint2*)(dst + (lane + w*32)*4) = st;
    }
    if (MODE && lane==0) g_minv[row] = inv;
}

// ---------------------------------------------------------------------------
// Kernel 3: fused bf16 HMMA GEMM (128q x 4096m per block, K=512) + streaming
// per-chunk top-5. grid = (NCH, NQ/QT). Q tile lives in SMEM for full K.
// ---------------------------------------------------------------------------
__global__ void __launch_bounds__(256,1) sim_topk_kernel(){
    extern __shared__ __align__(16) char smraw[];
    __nv_bfloat16* sQ  = (__nv_bfloat16*)smraw;
    __nv_bfloat16* sM  = (__nv_bfloat16*)(smraw + QT*SQ_STRIDE*2);
    float*         sSim= (float*)(smraw + QT*SQ_STRIDE*2 + 2*NT*SM_STRIDE*2);

    const int tid  = threadIdx.x;
    const int lane = tid & 31;
    const int wid  = tid >> 5;
    const int chunk = blockIdx.x;
    const int qbase = blockIdx.y * QT;
    const int mbase = chunk * MCHUNK;

    // Load Q tile (128 x 512 bf16) into SMEM, padded rows (conflict-free ldmatrix).
    const uint4* gq = (const uint4*)g_qn;   // 8 bf16 per uint4, 64 per row
    #pragma unroll
    for (int i=0; i<(QT*64)/256; i++){
        int idx = tid + i*256;
        int r = idx >> 6, c = idx & 63;
        uint4 val = gq[(size_t)(qbase + r)*64 + c];
        *(uint4*)(sQ + r*SQ_STRIDE + c*8) = val;
    }

    const int wq = (wid & 1) * 64;   // warp's 64-query slab
    const int wn = (wid >> 1) * 16;  // warp's 16-memory-col slab

    // Running top-5 (only threads < 128 use it; kept in registers)
    float s0=-2.f,s1=-2.f,s2=-2.f,s3=-2.f,s4=-2.f;
    int   i0=0,i1=0,i2=0,i3=0,i4=0;

    const uint4* gm = (const uint4*)g_mn;
    const int r0 = tid >> 3,       c0 = tid & 7;  // 512 uint4 per M-tile k-chunk: 2/thread
    const int r1 = (tid+256) >> 3;                // second item, same c

    __syncthreads();

    for (int mt=0; mt<MT_PER; mt++){
        const int mrow0 = mbase + mt*NT;
        float acc[4][2][4];
        #pragma unroll
        for (int a=0;a<4;a++)
            #pragma unroll
            for (int b=0;b<2;b++)
                #pragma unroll
                for (int d=0;d<4;d++) acc[a][b][d]=0.f;

        // Prefetch k-chunk 0 into regs, stage to buffer 0
        uint4 pa = gm[(size_t)(mrow0+r0)*64 + c0];
        uint4 pb = gm[(size_t)(mrow0+r1)*64 + c0];
        *(uint4*)(sM + r0*SM_STRIDE + c0*8) = pa;
        *(uint4*)(sM + r1*SM_STRIDE + c0*8) = pb;
        __syncthreads();

        #pragma unroll
        for (int kc=0; kc<NKC; kc++){
            if (kc+1 < NKC){
                pa = gm[(size_t)(mrow0+r0)*64 + (kc+1)*8 + c0];
                pb = gm[(size_t)(mrow0+r1)*64 + (kc+1)*8 + c0];
            }
            const __nv_bfloat16* mb = sM + (kc & 1)*(NT*SM_STRIDE);
            #pragma unroll
            for (int k16=0; k16<KC/16; k16++){
                // B fragments: memory rows are k-contiguous == col-major B. No .trans.
                uint32_t bfr[2][2];
                #pragma unroll
                for (int nt=0; nt<2; nt++){
                    int brow = wn + nt*8 + (lane & 7);
                    int bk   = k16*16 + ((lane >> 3) & 1)*8;
                    uint32_t ba = smem_u32(mb + brow*SM_STRIDE + bk);
                    asm volatile("ldmatrix.sync.aligned.m8n8.x2.shared.b16 {%0,%1}, [%2];"
                                 : "=r"(bfr[nt][0]), "=r"(bfr[nt][1]) : "r"(ba));
                }
                #pragma unroll
                for (int qt=0; qt<4; qt++){
                    uint32_t a0,a1,a2,a3;
                    int arow = wq + qt*16 + (lane & 15);
                    int ak   = kc*KC + k16*16 + (lane >> 4)*8;
                    uint32_t aa = smem_u32(sQ + arow*SQ_STRIDE + ak);
                    asm volatile("ldmatrix.sync.aligned.m8n8.x4.shared.b16 {%0,%1,%2,%3}, [%4];"
                                 : "=r"(a0),"=r"(a1),"=r"(a2),"=r"(a3) : "r"(aa));
                    #pragma unroll
                    for (int nt=0; nt<2; nt++){
                        asm volatile(
                          "mma.sync.aligned.m16n8k16.row.col.f32.bf16.bf16.f32 "
                          "{%0,%1,%2,%3}, {%4,%5,%6,%7}, {%8,%9}, {%0,%1,%2,%3};"
                          : "+f"(acc[qt][nt][0]),"+f"(acc[qt][nt][1]),
                            "+f"(acc[qt][nt][2]),"+f"(acc[qt][nt][3])
                          : "r"(a0),"r"(a1),"r"(a2),"r"(a3),
                            "r"(bfr[nt][0]),"r"(bfr[nt][1]));
                    }
                }
            }
            if (kc+1 < NKC){
                __nv_bfloat16* db = sM + ((kc+1)&1)*(NT*SM_STRIDE);
                *(uint4*)(db + r0*SM_STRIDE + c0*8) = pa;
                *(uint4*)(db + r1*SM_STRIDE + c0*8) = pb;
            }
            __syncthreads();
        }

        // Spill 128x64 score tile to SMEM (mma D-fragment layout).
        #pragma unroll
        for (int qt=0; qt<4; qt++){
            #pragma unroll
            for (int nt=0; nt<2; nt++){
                int r = wq + qt*16 + (lane >> 2);
                int c = wn + nt*8  + (lane & 3)*2;
                sSim[r*SS_STRIDE + c]         = acc[qt][nt][0];
                sSim[r*SS_STRIDE + c + 1]     = acc[qt][nt][1];
                sSim[(r+8)*SS_STRIDE + c]     = acc[qt][nt][2];
                sSim[(r+8)*SS_STRIDE + c + 1] = acc[qt][nt][3];
            }
        }
        __syncthreads();

        // 128 scan threads update running top-5 (strict >, earlier index wins ties).
        if (tid < QT){
            const float* row = sSim + tid*SS_STRIDE;
            #pragma unroll 4
            for (int c=0; c<NT; c++){
                float v = row[c];
                int id = mrow0 + c;
                if (v > s4){
                    if (v > s2){
                        if (v > s1){
                            if (v > s0){ s4=s3;i4=i3; s3=s2;i3=i2; s2=s1;i2=i1; s1=s0;i1=i0; s0=v;i0=id; }
                            else       { s4=s3;i4=i3; s3=s2;i3=i2; s2=s1;i2=i1; s1=v;i1=id; }
                        } else         { s4=s3;i4=i3; s3=s2;i3=i2; s2=v;i2=id; }
                    } else {
                        if (v > s3)    { s4=s3;i4=i3; s3=v;i3=id; }
                        else           { s4=v;i4=id; }
                    }
                }
            }
        }
        __syncthreads();
    }

    if (tid < QT){
        int q = qbase + tid;
        float* cs = g_cscore + (size_t)q*NCAND + chunk*TOPK;
        int*   ci = g_cidx   + (size_t)q*NCAND + chunk*TOPK;
        cs[0]=s0; cs[1]=s1; cs[2]=s2; cs[3]=s3; cs[4]=s4;
        ci[0]=i0; ci[1]=i1; ci[2]=i2; ci[3]=i3; ci[4]=i4;
    }
}

// ---------------------------------------------------------------------------
// Kernel 4: exact fp32 rescore of 40 candidates, true top-5, softmax, gather,
// out = x + 0.5 * retrieved. One warp per query.
// ---------------------------------------------------------------------------
__global__ void merge_kernel(const float* __restrict__ x,
                             const float* __restrict__ mem,
                             float* __restrict__ out){
    int gw   = (blockIdx.x*blockDim.x + threadIdx.x) >> 5;
    int lane = threadIdx.x & 31;
    if (gw >= NQ) return;

    const float4* xr = (const float4*)(x + (size_t)gw*CDIM);
    float4 xv[4];
    float ss = 0.f;
    #pragma unroll
    for (int w=0; w<4; w++){
        xv[w] = xr[lane + w*32];
        ss += xv[w].x*xv[w].x + xv[w].y*xv[w].y + xv[w].z*xv[w].z + xv[w].w*xv[w].w;
    }
    ss = warp_sum(ss);
    float qinv = 1.0f / fmaxf(sqrtf(ss), 1e-12f);

    float ts[TOPK]; int ti[TOPK];
    #pragma unroll
    for (int r=0;r<TOPK;r++){ ts[r]=-2.f; ti[r]=0; }

    for (int c=0; c<NCAND; c++){
        int idx = g_cidx[(size_t)gw*NCAND + c];
        const float4* mr = (const float4*)(mem + (size_t)idx*CDIM);
        float d = 0.f;
        #pragma unroll
        for (int w=0; w<4; w++){
            float4 mv = mr[lane + w*32];
            d += xv[w].x*mv.x + xv[w].y*mv.y + xv[w].z*mv.z + xv[w].w*mv.w;
        }
        d = warp_sum(d);
        float sc = d * qinv * g_minv[idx];
        if (sc > ts[TOPK-1]){
            ts[TOPK-1]=sc; ti[TOPK-1]=idx;
            #pragma unroll
            for (int r=TOPK-1; r>0; r--){
                if (ts[r] > ts[r-1]){
                    float t=ts[r]; ts[r]=ts[r-1]; ts[r-1]=t;
                    int   u=ti[r]; ti[r]=ti[r-1]; ti[r-1]=u;
                }
            }
        }
    }

    float wv[TOPK], sum=0.f;
    #pragma unroll
    for (int r=0;r<TOPK;r++){ wv[r] = expf(ts[r]-ts[0]); sum += wv[r]; }
    float isum = 1.0f/sum;

    float4 o[4];
    #pragma unroll
    for (int w4=0; w4<4; w4++) o[w4] = xv[w4];
    #pragma unroll
    for (int r=0; r<TOPK; r++){
        float wr = 0.5f * wv[r] * isum;
        const float4* mr = (const float4*)(mem + (size_t)ti[r]*CDIM);
        #pragma unroll
        for (int w4=0; w4<4; w4++){
            float4 mv = mr[lane + w4*32];
            o[w4].x += wr*mv.x; o[w4].y += wr*mv.y;
            o[w4].z += wr*mv.z; o[w4].w += wr*mv.w;
        }
    }
    float4* orow = (float4*)(out + (size_t)gw*CDIM);
    #pragma unroll
    for (int w4=0; w4<4; w4++) orow[lane + w4*32] = o[w4];
}

// ---------------------------------------------------------------------------
extern "C" void kernel_launch(void* const* d_in, const int* in_sizes, int n_in,
                              void* d_out, int out_size){
    const float* x   = (const float*)d_in[0];   // [4,2048,512]
    const float* mem = (const float*)d_in[1];   // [32768,512]
    float* out = (float*)d_out;

    cudaFuncSetAttribute(sim_topk_kernel,
                         cudaFuncAttributeMaxDynamicSharedMemorySize, SMEM_BYTES);

    normalize_kernel<0><<<NQ/8, 256>>>(x);
    normalize_kernel<1><<<MROWS/8, 256>>>(mem);
    sim_topk_kernel<<<dim3(NCH, NQ/QT), 256, SMEM_BYTES>>>();
    merge_kernel<<<(NQ*32)/256, 256>>>(x, mem, out);
}